// round 7
// baseline (speedup 1.0000x reference)
#include <cuda_runtime.h>
#include <math.h>

// Problem constants (fixed by the dataset)
#define NCAP 100000
#define ECAP 1600000
#define DIM  64
#define HID  128

// ---------------- scratch (device globals; no runtime allocation) ----------
static __device__ __align__(128) int   d_cnt[NCAP];
static __device__ __align__(128) int   d_rowptr[NCAP + 1];
static __device__ __align__(128) int   d_cursor[NCAP];
static __device__ __align__(128) int   d_bsum[256];
static __device__ __align__(128) int   d_col[ECAP];
static __device__ __align__(128) float d_dinv[NCAP];
static __device__ __align__(128) float d_invdeg[NCAP];
static __device__ __align__(128) float d_x[NCAP * DIM];      // renormed entity emb
static __device__ __align__(128) float d_agg1[NCAP * DIM];   // Ahat(x)
static __device__ __align__(128) float d_h1[(size_t)NCAP * HID]; // relu(Ahat(x)W1+b1)
static __device__ __align__(128) float d_g[NCAP * DIM];      // h1 @ W2

// ---------------- degree counting ------------------------------------------
__global__ void zero_cnt_kernel(int n) {
    int i = blockIdx.x * blockDim.x + threadIdx.x;
    if (i < n) d_cnt[i] = 0;
}

__global__ void count_deg_kernel(const int* __restrict__ dst, int E) {
    int e = blockIdx.x * blockDim.x + threadIdx.x;
    if (e < E) atomicAdd(&d_cnt[dst[e]], 1);
}

// ---------------- prefix sum (chunked) --------------------------------------
// Each block scans a 1024-element chunk of d_cnt; writes chunk-local exclusive
// prefix to d_rowptr and chunk total to d_bsum.
__global__ void scan_chunk_kernel(int n) {
    __shared__ int s[1024];
    int t = threadIdx.x;
    int i = blockIdx.x * 1024 + t;
    int v = (i < n) ? d_cnt[i] : 0;
    s[t] = v;
    __syncthreads();
    // Hillis-Steele inclusive scan
    for (int off = 1; off < 1024; off <<= 1) {
        int add = (t >= off) ? s[t - off] : 0;
        __syncthreads();
        s[t] += add;
        __syncthreads();
    }
    if (i < n) d_rowptr[i] = s[t] - v;   // exclusive
    if (t == 1023) d_bsum[blockIdx.x] = s[1023];
}

__global__ void scan_bsums_kernel(int nb) {
    if (threadIdx.x == 0 && blockIdx.x == 0) {
        int run = 0;
        for (int b = 0; b < nb; b++) { int v = d_bsum[b]; d_bsum[b] = run; run += v; }
    }
}

__global__ void finalize_rowptr_kernel(int n, int Etot) {
    int i = blockIdx.x * blockDim.x + threadIdx.x;
    if (i < n) {
        int rp = d_rowptr[i] + d_bsum[i >> 10];
        d_rowptr[i] = rp;
        d_cursor[i] = rp;
        float deg = (float)(d_cnt[i] + 1);   // +1 self loop
        d_dinv[i]   = rsqrtf(deg);
        d_invdeg[i] = 1.0f / deg;
    }
    if (i == 0) d_rowptr[n] = Etot;
}

__global__ void fill_csr_kernel(const int* __restrict__ src,
                                const int* __restrict__ dst, int E) {
    int e = blockIdx.x * blockDim.x + threadIdx.x;
    if (e < E) {
        int d = dst[e];
        int p = atomicAdd(&d_cursor[d], 1);
        d_col[p] = src[e];
    }
}

// ---------------- entity renorm (max_norm = 1) ------------------------------
// one warp per row; lane holds float2 of the 64-dim row
__global__ void renorm_entities_kernel(const float* __restrict__ emb, int n) {
    int gtid = blockIdx.x * blockDim.x + threadIdx.x;
    int row = gtid >> 5;
    int lane = gtid & 31;
    if (row >= n) return;
    float2 v = *(const float2*)(emb + (size_t)row * DIM + lane * 2);
    float ss = v.x * v.x + v.y * v.y;
    #pragma unroll
    for (int o = 16; o; o >>= 1) ss += __shfl_xor_sync(0xffffffffu, ss, o);
    float nrm = sqrtf(ss);
    float sc = fminf(1.0f, 1.0f / fmaxf(nrm, 1e-12f));
    float2 o2 = make_float2(v.x * sc, v.y * sc);
    *(float2*)(d_x + (size_t)row * DIM + lane * 2) = o2;
}

// ---------------- aggregation: d_agg1 = Ahat(d_x) ---------------------------
// one warp per dst row; lane = float2 of the 64-dim feature
__global__ void aggregate1_kernel(int n) {
    int gtid = blockIdx.x * blockDim.x + threadIdx.x;
    int r = gtid >> 5;
    int lane = gtid & 31;
    if (r >= n) return;
    int beg = d_rowptr[r], end = d_rowptr[r + 1];
    float2 acc = make_float2(0.f, 0.f);
    for (int e = beg; e < end; e++) {
        int s = d_col[e];
        float w = d_dinv[s];
        float2 xs = *(const float2*)(d_x + (size_t)s * DIM + lane * 2);
        acc.x = fmaf(w, xs.x, acc.x);
        acc.y = fmaf(w, xs.y, acc.y);
    }
    float di = d_dinv[r], id = d_invdeg[r];
    float2 self = *(const float2*)(d_x + (size_t)r * DIM + lane * 2);
    float2 o = make_float2(di * acc.x + id * self.x,
                           di * acc.y + id * self.y);
    *(float2*)(d_agg1 + (size_t)r * DIM + lane * 2) = o;
}

// ---------------- register-tiled SGEMM body ---------------------------------
// C[M,N] = act(A[M,K] @ W[K,N] (+ bias)); BM=128 rows/block, 256 threads,
// TM=8 x TN=N/16 micro-tile per thread, K consumed in chunks of 32.
template <int N, int K, bool RELU, bool HB>
__device__ __forceinline__ void gemm_body(const float* __restrict__ A,
                                          const float* __restrict__ W,
                                          const float* __restrict__ bias,
                                          float* __restrict__ C, int M) {
    constexpr int BM = 128, KC = 32, TM = 8, TN = N / 16;
    __shared__ __align__(16) float sA[KC][BM + 4];  // k-major, padded
    __shared__ __align__(16) float sW[KC][N];
    const int tid = threadIdx.x;
    const int tx = tid & 15, ty = tid >> 4;
    const int rowBase = blockIdx.x * BM;
    const int r0 = ty * TM, c0 = tx * TN;

    float acc[TM][TN];
    #pragma unroll
    for (int i = 0; i < TM; i++)
        #pragma unroll
        for (int j = 0; j < TN; j++) acc[i][j] = 0.f;

    for (int kc = 0; kc < K; kc += KC) {
        // load A chunk (transposed into smem): BM x KC = 1024 float4 loads
        #pragma unroll
        for (int t = tid; t < BM * (KC / 4); t += 256) {
            int r = t >> 3;       // KC/4 == 8
            int k4 = t & 7;
            float4 v = make_float4(0.f, 0.f, 0.f, 0.f);
            int gr = rowBase + r;
            if (gr < M) v = *(const float4*)(A + (size_t)gr * K + kc + k4 * 4);
            sA[k4 * 4 + 0][r] = v.x;
            sA[k4 * 4 + 1][r] = v.y;
            sA[k4 * 4 + 2][r] = v.z;
            sA[k4 * 4 + 3][r] = v.w;
        }
        // load W chunk: KC x N
        #pragma unroll
        for (int t = tid; t < KC * (N / 4); t += 256) {
            int k = t / (N / 4), c4 = t % (N / 4);
            *(float4*)&sW[k][c4 * 4] =
                *(const float4*)(W + (size_t)(kc + k) * N + c4 * 4);
        }
        __syncthreads();

        #pragma unroll 4
        for (int k = 0; k < KC; k++) {
            float a[TM], b[TN];
            const float4* ap = (const float4*)&sA[k][r0];
            float4 a0 = ap[0], a1 = ap[1];
            a[0] = a0.x; a[1] = a0.y; a[2] = a0.z; a[3] = a0.w;
            a[4] = a1.x; a[5] = a1.y; a[6] = a1.z; a[7] = a1.w;
            const float4* bp = (const float4*)&sW[k][c0];
            #pragma unroll
            for (int j4 = 0; j4 < TN / 4; j4++) {
                float4 bv = bp[j4];
                b[j4 * 4 + 0] = bv.x; b[j4 * 4 + 1] = bv.y;
                b[j4 * 4 + 2] = bv.z; b[j4 * 4 + 3] = bv.w;
            }
            #pragma unroll
            for (int i = 0; i < TM; i++)
                #pragma unroll
                for (int j = 0; j < TN; j++)
                    acc[i][j] = fmaf(a[i], b[j], acc[i][j]);
        }
        __syncthreads();
    }

    // epilogue (vectorized stores)
    #pragma unroll
    for (int i = 0; i < TM; i++) {
        int gr = rowBase + r0 + i;
        if (gr < M) {
            #pragma unroll
            for (int j4 = 0; j4 < TN / 4; j4++) {
                float4 v;
                float* a4 = &acc[i][j4 * 4];
                v.x = a4[0]; v.y = a4[1]; v.z = a4[2]; v.w = a4[3];
                if (HB) {
                    const float4 bb = *(const float4*)(bias + c0 + j4 * 4);
                    v.x += bb.x; v.y += bb.y; v.z += bb.z; v.w += bb.w;
                }
                if (RELU) {
                    v.x = fmaxf(v.x, 0.f); v.y = fmaxf(v.y, 0.f);
                    v.z = fmaxf(v.z, 0.f); v.w = fmaxf(v.w, 0.f);
                }
                *(float4*)(C + (size_t)gr * N + c0 + j4 * 4) = v;
            }
        }
    }
}

__global__ __launch_bounds__(256, 2)
void gemm1_kernel(const float* __restrict__ W1, const float* __restrict__ b1, int M) {
    gemm_body<HID, DIM, /*RELU=*/true, /*HB=*/true>(d_agg1, W1, b1, d_h1, M);
}

__global__ __launch_bounds__(256, 2)
void gemm2_kernel(const float* __restrict__ W2, int M) {
    gemm_body<DIM, HID, /*RELU=*/false, /*HB=*/false>(d_h1, W2, nullptr, d_g, M);
}

// ---------------- final: agg2 restricted to batch items + user dot ----------
// out[b] = sigmoid( dot(renorm(user_emb[u[b]]), Ahat(g)[i[b]] + b2) )
__global__ void final_kernel(const int* __restrict__ u,
                             const int* __restrict__ it,
                             const float* __restrict__ user_emb,
                             const float* __restrict__ b2,
                             float* __restrict__ out, int B) {
    int gtid = blockIdx.x * blockDim.x + threadIdx.x;
    int w = gtid >> 5;
    int lane = gtid & 31;
    if (w >= B) return;

    int r = it[w];
    int beg = d_rowptr[r], end = d_rowptr[r + 1];
    float2 acc = make_float2(0.f, 0.f);
    for (int e = beg; e < end; e++) {
        int s = d_col[e];
        float wt = d_dinv[s];
        float2 gs = *(const float2*)(d_g + (size_t)s * DIM + lane * 2);
        acc.x = fmaf(wt, gs.x, acc.x);
        acc.y = fmaf(wt, gs.y, acc.y);
    }
    float di = d_dinv[r], id = d_invdeg[r];
    float2 gr = *(const float2*)(d_g + (size_t)r * DIM + lane * 2);
    float2 item = make_float2(di * acc.x + id * gr.x + b2[lane * 2 + 0],
                              di * acc.y + id * gr.y + b2[lane * 2 + 1]);

    int uu = u[w];
    float2 uv = *(const float2*)(user_emb + (size_t)uu * DIM + lane * 2);
    float ss = uv.x * uv.x + uv.y * uv.y;
    #pragma unroll
    for (int o = 16; o; o >>= 1) ss += __shfl_xor_sync(0xffffffffu, ss, o);
    float sc = fminf(1.0f, 1.0f / fmaxf(sqrtf(ss), 1e-12f));

    float dot = (uv.x * sc) * item.x + (uv.y * sc) * item.y;
    #pragma unroll
    for (int o = 16; o; o >>= 1) dot += __shfl_xor_sync(0xffffffffu, dot, o);

    if (lane == 0) out[w] = 1.0f / (1.0f + expf(-dot));
}

// ---------------- launch ----------------------------------------------------
extern "C" void kernel_launch(void* const* d_in, const int* in_sizes, int n_in,
                              void* d_out, int out_size) {
    const int*   u          = (const int*)d_in[0];
    const int*   it         = (const int*)d_in[1];
    const int*   edges      = (const int*)d_in[2];
    const float* user_emb   = (const float*)d_in[3];
    const float* entity_emb = (const float*)d_in[4];
    const float* W1         = (const float*)d_in[5];
    const float* b1         = (const float*)d_in[6];
    const float* W2         = (const float*)d_in[7];
    const float* b2         = (const float*)d_in[8];
    float*       out        = (float*)d_out;

    int B = in_sizes[0];
    int E = in_sizes[2] / 2;
    int n = in_sizes[4] / DIM;
    if (n > NCAP) n = NCAP;
    if (E > ECAP) E = ECAP;

    const int* src = edges;
    const int* dst = edges + E;

    const int T = 256;

    // degree counts
    zero_cnt_kernel<<<(n + T - 1) / T, T>>>(n);
    count_deg_kernel<<<(E + T - 1) / T, T>>>(dst, E);

    // CSR build
    int nb = (n + 1023) / 1024;
    scan_chunk_kernel<<<nb, 1024>>>(n);
    scan_bsums_kernel<<<1, 32>>>(nb);
    finalize_rowptr_kernel<<<(n + T - 1) / T, T>>>(n, E);
    fill_csr_kernel<<<(E + T - 1) / T, T>>>(src, dst, E);

    // renorm entities (warp per row, 8 rows per block)
    renorm_entities_kernel<<<(n + 7) / 8, T>>>(entity_emb, n);

    // layer-1 aggregation in DIM space
    aggregate1_kernel<<<(n + 7) / 8, T>>>(n);

    // h1 = relu(agg1 @ W1 + b1); g = h1 @ W2
    int gblocks = (n + 127) / 128;
    gemm1_kernel<<<gblocks, 256>>>(W1, b1, n);
    gemm2_kernel<<<gblocks, 256>>>(W2, n);

    // restricted layer-2 aggregation fused with user dot + sigmoid
    final_kernel<<<(B + 7) / 8, T>>>(u, it, user_emb, b2, out, B);
}

// round 8
// speedup vs baseline: 1.1463x; 1.1463x over previous
#include <cuda_runtime.h>
#include <math.h>

// Problem constants (fixed by the dataset)
#define NCAP 100000
#define ECAP 1600000
#define DIM  64
#define HID  128

// ---------------- scratch (device globals; no runtime allocation) ----------
static __device__ __align__(128) int   d_cnt[NCAP];
static __device__ __align__(128) int   d_rowptr[NCAP + 1];
static __device__ __align__(128) int   d_cursor[NCAP];
static __device__ __align__(128) int   d_bsum[256];
static __device__ __align__(128) int   d_col[ECAP];
static __device__ __align__(128) float d_dinv[NCAP];
static __device__ __align__(128) float d_invdeg[NCAP];
static __device__ __align__(128) float d_x[NCAP * DIM];      // renormed entity emb
static __device__ __align__(128) float d_agg1[NCAP * DIM];   // Ahat(x)
static __device__ __align__(128) float d_g[NCAP * DIM];      // (Ahat(x)W1+b1)+ @ W2

// ---------------- f32x2 packed math (Blackwell FFMA2) -----------------------
__device__ __forceinline__ unsigned long long pk2(float lo, float hi) {
    unsigned long long r;
    asm("mov.b64 %0, {%1, %2};" : "=l"(r) : "r"(__float_as_uint(lo)), "r"(__float_as_uint(hi)));
    return r;
}
__device__ __forceinline__ unsigned long long fma2(unsigned long long a,
                                                   unsigned long long b,
                                                   unsigned long long c) {
    unsigned long long d;
    asm("fma.rn.f32x2 %0, %1, %2, %3;" : "=l"(d) : "l"(a), "l"(b), "l"(c));
    return d;
}
__device__ __forceinline__ float2 upk2(unsigned long long v) {
    unsigned int lo, hi;
    asm("mov.b64 {%0, %1}, %2;" : "=r"(lo), "=r"(hi) : "l"(v));
    return make_float2(__uint_as_float(lo), __uint_as_float(hi));
}

// ---------------- degree counting ------------------------------------------
__global__ void zero_cnt_kernel(int n) {
    int i = blockIdx.x * blockDim.x + threadIdx.x;
    if (i < n) d_cnt[i] = 0;
}

__global__ void count_deg_kernel(const int* __restrict__ dst, int E) {
    int e = blockIdx.x * blockDim.x + threadIdx.x;
    if (e < E) atomicAdd(&d_cnt[dst[e]], 1);
}

// ---------------- prefix sum (chunked) --------------------------------------
__global__ void scan_chunk_kernel(int n) {
    __shared__ int s[1024];
    int t = threadIdx.x;
    int i = blockIdx.x * 1024 + t;
    int v = (i < n) ? d_cnt[i] : 0;
    s[t] = v;
    __syncthreads();
    for (int off = 1; off < 1024; off <<= 1) {
        int add = (t >= off) ? s[t - off] : 0;
        __syncthreads();
        s[t] += add;
        __syncthreads();
    }
    if (i < n) d_rowptr[i] = s[t] - v;   // exclusive
    if (t == 1023) d_bsum[blockIdx.x] = s[1023];
}

// parallel exclusive scan of block sums (nb <= 128), one block of 128 threads
__global__ void scan_bsums_kernel(int nb) {
    __shared__ int ws[4];
    int t = threadIdx.x;
    int lane = t & 31, w = t >> 5;
    int v = (t < nb) ? d_bsum[t] : 0;
    int s = v;
    #pragma unroll
    for (int o = 1; o < 32; o <<= 1) {
        int u = __shfl_up_sync(0xffffffffu, s, o);
        if (lane >= o) s += u;
    }
    if (lane == 31) ws[w] = s;
    __syncthreads();
    int add = 0;
    #pragma unroll
    for (int i = 0; i < 4; i++) if (i < w) add += ws[i];
    if (t < nb) d_bsum[t] = s - v + add;   // exclusive
}

__global__ void finalize_rowptr_kernel(int n, int Etot) {
    int i = blockIdx.x * blockDim.x + threadIdx.x;
    if (i < n) {
        int rp = d_rowptr[i] + d_bsum[i >> 10];
        d_rowptr[i] = rp;
        d_cursor[i] = rp;
        float deg = (float)(d_cnt[i] + 1);   // +1 self loop
        d_dinv[i]   = rsqrtf(deg);
        d_invdeg[i] = 1.0f / deg;
    }
    if (i == 0) d_rowptr[n] = Etot;
}

__global__ void fill_csr_kernel(const int* __restrict__ src,
                                const int* __restrict__ dst, int E) {
    int e = blockIdx.x * blockDim.x + threadIdx.x;
    if (e < E) {
        int d = dst[e];
        int p = atomicAdd(&d_cursor[d], 1);
        d_col[p] = src[e];
    }
}

// ---------------- entity renorm (max_norm = 1) ------------------------------
__global__ void renorm_entities_kernel(const float* __restrict__ emb, int n) {
    int gtid = blockIdx.x * blockDim.x + threadIdx.x;
    int row = gtid >> 5;
    int lane = gtid & 31;
    if (row >= n) return;
    float2 v = *(const float2*)(emb + (size_t)row * DIM + lane * 2);
    float ss = v.x * v.x + v.y * v.y;
    #pragma unroll
    for (int o = 16; o; o >>= 1) ss += __shfl_xor_sync(0xffffffffu, ss, o);
    float nrm = sqrtf(ss);
    float sc = fminf(1.0f, 1.0f / fmaxf(nrm, 1e-12f));
    float2 o2 = make_float2(v.x * sc, v.y * sc);
    *(float2*)(d_x + (size_t)row * DIM + lane * 2) = o2;
}

// ---------------- aggregation: d_agg1 = Ahat(d_x) ---------------------------
__global__ void aggregate1_kernel(int n) {
    int gtid = blockIdx.x * blockDim.x + threadIdx.x;
    int r = gtid >> 5;
    int lane = gtid & 31;
    if (r >= n) return;
    int beg = d_rowptr[r], end = d_rowptr[r + 1];
    float2 acc = make_float2(0.f, 0.f);
    for (int e = beg; e < end; e++) {
        int s = d_col[e];
        float w = d_dinv[s];
        float2 xs = *(const float2*)(d_x + (size_t)s * DIM + lane * 2);
        acc.x = fmaf(w, xs.x, acc.x);
        acc.y = fmaf(w, xs.y, acc.y);
    }
    float di = d_dinv[r], id = d_invdeg[r];
    float2 self = *(const float2*)(d_x + (size_t)r * DIM + lane * 2);
    float2 o = make_float2(di * acc.x + id * self.x,
                           di * acc.y + id * self.y);
    *(float2*)(d_agg1 + (size_t)r * DIM + lane * 2) = o;
}

// ---------------- fused GEMM1+GEMM2 with f32x2 -------------------------------
// Per block: rows [rowBase, rowBase+128)
//   stage 1: H = relu(A[128,64] @ W1[64,128] + b1)  -> smem (row-major, pad 132)
//   stage 2: G = H[128,128] @ W2[128,64]            -> d_g
// smem: sA[128][68] rowmajor | sW1 paired [64][128] | sW2 [128][64] | sH[128][132]
#define SA_STRIDE 68
#define SH_STRIDE 132
#define FUSED_SMEM_FLOATS (128 * SA_STRIDE + 64 * 128 + 128 * 64 + 128 * SH_STRIDE)
#define FUSED_SMEM_BYTES  (FUSED_SMEM_FLOATS * 4)

__global__ __launch_bounds__(256, 1)
void gemm_fused_kernel(const float* __restrict__ W1, const float* __restrict__ b1,
                       const float* __restrict__ W2, int M) {
    extern __shared__ float smem[];
    float* sA  = smem;                         // [128][SA_STRIDE]
    float* sW1 = sA  + 128 * SA_STRIDE;        // paired layout [64][128]
    float* sW2 = sW1 + 64 * 128;               // [128][64]
    float* sH  = sW2 + 128 * 64;               // [128][SH_STRIDE]

    const int tid = threadIdx.x;
    const int tx = tid & 15, ty = tid >> 4;
    const int r0 = ty * 8;
    const int rowBase = blockIdx.x * 128;

    // --- load A tile (row-major, float4, coalesced) ---
    #pragma unroll
    for (int t = tid; t < 128 * 16; t += 256) {
        int r = t >> 4, k4 = t & 15;
        float4 v = make_float4(0.f, 0.f, 0.f, 0.f);
        int gr = rowBase + r;
        if (gr < M) v = *(const float4*)(d_agg1 + (size_t)gr * DIM + k4 * 4);
        *(float4*)&sA[r * SA_STRIDE + k4 * 4] = v;
    }
    // --- load W1 into pre-paired layout: pair (c, c+16) adjacent ---
    // c = txp + 16*m  ->  slot = 2*((m>>1)*16 + txp) + (m&1)
    #pragma unroll
    for (int t = tid; t < 64 * 128; t += 256) {
        int k = t >> 7, c = t & 127;
        int txp = c & 15, m = c >> 4;
        int slot = (((m >> 1) * 16 + txp) << 1) + (m & 1);
        sW1[k * 128 + slot] = W1[t];
    }
    // --- load W2 (plain copy, float4) ---
    #pragma unroll
    for (int t = tid; t < 128 * 16; t += 256) {
        *(float4*)&sW2[t * 4] = *(const float4*)(W2 + t * 4);
    }
    __syncthreads();

    // ---- stage 1: acc[i][j] covers row r0+i, col pair (tx+32j, tx+32j+16) ----
    unsigned long long acc[8][4];
    #pragma unroll
    for (int i = 0; i < 8; i++)
        #pragma unroll
        for (int j = 0; j < 4; j++) acc[i][j] = 0ull;

    #pragma unroll 4
    for (int k = 0; k < 64; k++) {
        unsigned long long bd[4];
        #pragma unroll
        for (int j = 0; j < 4; j++)
            bd[j] = *(const unsigned long long*)&sW1[k * 128 + ((j * 16 + tx) << 1)];
        #pragma unroll
        for (int i = 0; i < 8; i++) {
            float a = sA[(r0 + i) * SA_STRIDE + k];
            unsigned long long ad = pk2(a, a);
            #pragma unroll
            for (int j = 0; j < 4; j++)
                acc[i][j] = fma2(ad, bd[j], acc[i][j]);
        }
    }

    // bias + relu + write H to smem (scalar writes, interleaved cols: <=2-way)
    float b1c[8];
    #pragma unroll
    for (int j = 0; j < 4; j++) {
        b1c[j * 2]     = b1[tx + 32 * j];
        b1c[j * 2 + 1] = b1[tx + 32 * j + 16];
    }
    #pragma unroll
    for (int i = 0; i < 8; i++) {
        int rr = (r0 + i) * SH_STRIDE;
        #pragma unroll
        for (int j = 0; j < 4; j++) {
            float2 v = upk2(acc[i][j]);
            int c = tx + 32 * j;
            sH[rr + c]      = fmaxf(v.x + b1c[j * 2], 0.f);
            sH[rr + c + 16] = fmaxf(v.y + b1c[j * 2 + 1], 0.f);
        }
    }
    __syncthreads();

    // ---- stage 2: acc2[i][j] covers row r0+i, cols (4tx+2j, 4tx+2j+1) ----
    unsigned long long acc2[8][2];
    #pragma unroll
    for (int i = 0; i < 8; i++) { acc2[i][0] = 0ull; acc2[i][1] = 0ull; }

    #pragma unroll 4
    for (int k = 0; k < 128; k++) {
        unsigned long long bd0 = *(const unsigned long long*)&sW2[k * 64 + 4 * tx];
        unsigned long long bd1 = *(const unsigned long long*)&sW2[k * 64 + 4 * tx + 2];
        #pragma unroll
        for (int i = 0; i < 8; i++) {
            float a = sH[(r0 + i) * SH_STRIDE + k];
            unsigned long long ad = pk2(a, a);
            acc2[i][0] = fma2(ad, bd0, acc2[i][0]);
            acc2[i][1] = fma2(ad, bd1, acc2[i][1]);
        }
    }

    // write G (float4, coalesced)
    #pragma unroll
    for (int i = 0; i < 8; i++) {
        int gr = rowBase + r0 + i;
        if (gr < M) {
            float2 v0 = upk2(acc2[i][0]);
            float2 v1 = upk2(acc2[i][1]);
            float4 o = make_float4(v0.x, v0.y, v1.x, v1.y);
            *(float4*)&d_g[(size_t)gr * DIM + 4 * tx] = o;
        }
    }
}

// ---------------- final: agg2 restricted to batch items + user dot ----------
__global__ void final_kernel(const int* __restrict__ u,
                             const int* __restrict__ it,
                             const float* __restrict__ user_emb,
                             const float* __restrict__ b2,
                             float* __restrict__ out, int B) {
    int gtid = blockIdx.x * blockDim.x + threadIdx.x;
    int w = gtid >> 5;
    int lane = gtid & 31;
    if (w >= B) return;

    int r = it[w];
    int beg = d_rowptr[r], end = d_rowptr[r + 1];
    float2 acc = make_float2(0.f, 0.f);
    for (int e = beg; e < end; e++) {
        int s = d_col[e];
        float wt = d_dinv[s];
        float2 gs = *(const float2*)(d_g + (size_t)s * DIM + lane * 2);
        acc.x = fmaf(wt, gs.x, acc.x);
        acc.y = fmaf(wt, gs.y, acc.y);
    }
    float di = d_dinv[r], id = d_invdeg[r];
    float2 gr = *(const float2*)(d_g + (size_t)r * DIM + lane * 2);
    float2 item = make_float2(di * acc.x + id * gr.x + b2[lane * 2 + 0],
                              di * acc.y + id * gr.y + b2[lane * 2 + 1]);

    int uu = u[w];
    float2 uv = *(const float2*)(user_emb + (size_t)uu * DIM + lane * 2);
    float ss = uv.x * uv.x + uv.y * uv.y;
    #pragma unroll
    for (int o = 16; o; o >>= 1) ss += __shfl_xor_sync(0xffffffffu, ss, o);
    float sc = fminf(1.0f, 1.0f / fmaxf(sqrtf(ss), 1e-12f));

    float dot = (uv.x * sc) * item.x + (uv.y * sc) * item.y;
    #pragma unroll
    for (int o = 16; o; o >>= 1) dot += __shfl_xor_sync(0xffffffffu, dot, o);

    if (lane == 0) out[w] = 1.0f / (1.0f + expf(-dot));
}

// ---------------- launch ----------------------------------------------------
extern "C" void kernel_launch(void* const* d_in, const int* in_sizes, int n_in,
                              void* d_out, int out_size) {
    const int*   u          = (const int*)d_in[0];
    const int*   it         = (const int*)d_in[1];
    const int*   edges      = (const int*)d_in[2];
    const float* user_emb   = (const float*)d_in[3];
    const float* entity_emb = (const float*)d_in[4];
    const float* W1         = (const float*)d_in[5];
    const float* b1         = (const float*)d_in[6];
    const float* W2         = (const float*)d_in[7];
    const float* b2         = (const float*)d_in[8];
    float*       out        = (float*)d_out;

    int B = in_sizes[0];
    int E = in_sizes[2] / 2;
    int n = in_sizes[4] / DIM;
    if (n > NCAP) n = NCAP;
    if (E > ECAP) E = ECAP;

    const int* src = edges;
    const int* dst = edges + E;

    const int T = 256;

    // degree counts
    zero_cnt_kernel<<<(n + T - 1) / T, T>>>(n);
    count_deg_kernel<<<(E + T - 1) / T, T>>>(dst, E);

    // CSR build
    int nb = (n + 1023) / 1024;
    scan_chunk_kernel<<<nb, 1024>>>(n);
    scan_bsums_kernel<<<1, 128>>>(nb);
    finalize_rowptr_kernel<<<(n + T - 1) / T, T>>>(n, E);
    fill_csr_kernel<<<(E + T - 1) / T, T>>>(src, dst, E);

    // renorm entities
    renorm_entities_kernel<<<(n + 7) / 8, T>>>(entity_emb, n);

    // layer-1 aggregation in DIM space
    aggregate1_kernel<<<(n + 7) / 8, T>>>(n);

    // fused g = relu(agg1@W1+b1) @ W2 with packed f32x2
    cudaFuncSetAttribute(gemm_fused_kernel,
                         cudaFuncAttributeMaxDynamicSharedMemorySize,
                         FUSED_SMEM_BYTES);
    int gblocks = (n + 127) / 128;
    gemm_fused_kernel<<<gblocks, 256, FUSED_SMEM_BYTES>>>(W1, b1, W2, n);

    // restricted layer-2 aggregation fused with user dot + sigmoid
    final_kernel<<<(B + 7) / 8, T>>>(u, it, user_emb, b2, out, B);
}